// round 1
// baseline (speedup 1.0000x reference)
#include <cuda_runtime.h>
#include <math.h>

// ---------------- problem constants ----------------
#define L_SEQ   2048
#define B_SZ    4
#define D_INF   2048
#define D_OUTF  2048
#define P_DIM   1024
#define H_HEADS 8
#define HD      128
#define M_ROWS  (L_SEQ * B_SZ)        // 8192
#define LN_EPS  1e-5f

// ---------------- scratch (device globals; no allocation allowed) ----------------
__device__ float g_q  [M_ROWS * P_DIM];        // 32 MB  : linear1 output / residual
__device__ float g_kv [M_ROWS * 2 * P_DIM];    // 64 MB  : linear2 output (K | V)
__device__ float g_att[M_ROWS * P_DIM];        // 32 MB  : attention output
__device__ float g_oln[M_ROWS * P_DIM];        // 32 MB  : rezero+LN output

// ============================================================================
// SGEMM:  C[M,N] = A[M,K] * B[N,K]^T      (A,B,C row-major, all dims % tile == 0)
// 128x128 tile, BK=8, 256 threads, 8x8 per-thread register tile.
// ============================================================================
#define GBM 128
#define GBN 128
#define GBK 8
#define GTM 8
#define GTN 8

__global__ void __launch_bounds__(256)
sgemm_abt(const float* __restrict__ A, const float* __restrict__ B,
          float* __restrict__ C, int M, int N, int K)
{
    __shared__ float As[GBK][GBM + 4];
    __shared__ float Bs[GBK][GBN + 4];

    const int tid = threadIdx.x;
    const int r0  = blockIdx.y * GBM;
    const int c0  = blockIdx.x * GBN;

    // loaders: 256 threads, each loads one float4 of A and of B per k-step
    const int lr = tid >> 1;          // 0..127
    const int lk = (tid & 1) << 2;    // 0 or 4
    const float* Ap = A + (long)(r0 + lr) * K + lk;
    const float* Bp = B + (long)(c0 + lr) * K + lk;

    const int ty = tid >> 4;          // 0..15
    const int tx = tid & 15;          // 0..15

    float acc[GTM][GTN] = {};

    for (int k0 = 0; k0 < K; k0 += GBK) {
        float4 a4 = *(const float4*)(Ap + k0);
        float4 b4 = *(const float4*)(Bp + k0);
        As[lk + 0][lr] = a4.x; As[lk + 1][lr] = a4.y;
        As[lk + 2][lr] = a4.z; As[lk + 3][lr] = a4.w;
        Bs[lk + 0][lr] = b4.x; Bs[lk + 1][lr] = b4.y;
        Bs[lk + 2][lr] = b4.z; Bs[lk + 3][lr] = b4.w;
        __syncthreads();

#pragma unroll
        for (int kk = 0; kk < GBK; kk++) {
            float ar[GTM], br[GTN];
#pragma unroll
            for (int i = 0; i < GTM; i++) ar[i] = As[kk][ty * GTM + i];
#pragma unroll
            for (int j = 0; j < GTN; j++) br[j] = Bs[kk][tx * GTN + j];
#pragma unroll
            for (int i = 0; i < GTM; i++)
#pragma unroll
                for (int j = 0; j < GTN; j++)
                    acc[i][j] += ar[i] * br[j];
        }
        __syncthreads();
    }

#pragma unroll
    for (int i = 0; i < GTM; i++) {
        float* Cp = C + (long)(r0 + ty * GTM + i) * N + c0 + tx * GTN;
#pragma unroll
        for (int j = 0; j < GTN; j += 4) {
            float4 v = make_float4(acc[i][j], acc[i][j + 1], acc[i][j + 2], acc[i][j + 3]);
            *(float4*)(Cp + j) = v;
        }
    }
}

// ============================================================================
// Causal flash attention, fp32.
// grid = (L/64, B*H). block = 256 threads (16x16). BM=BN=64, HD=128.
// q layout: q[(l*B+b)*P + h*HD + d];  kv: K at col h*HD+d, V at col P + h*HD + d.
// The reference mask is exactly causal(-1e9): for j<=i the added mask is 0.0f,
// for j>i softmax prob is exactly 0 in fp32 -> pure causal handling is
// bit-equivalent at the softmax output.
// ============================================================================
#define FBM  64
#define FBN  64
#define FSTR (HD + 4)      // padded smem stride for Q/K/V tiles
#define SSTR (FBN + 4)     // padded stride for the P tile

__global__ void __launch_bounds__(256)
flash_attn(const float* __restrict__ q, const float* __restrict__ kv,
           float* __restrict__ o)
{
    extern __shared__ float sm[];
    float* Qs = sm;                         // 64 * 132
    float* Ks = Qs + FBM * FSTR;            // 64 * 132
    float* Vs = Ks + FBN * FSTR;            // 64 * 132
    float* Ss = Vs + FBN * FSTR;            // 64 * 68

    const int tid = threadIdx.x;
    const int qb  = blockIdx.x;
    const int n   = blockIdx.y;             // b*H + h
    const int b   = n >> 3;                 // H = 8
    const int h   = n & 7;
    const int q0  = qb * FBM;
    const int ty  = tid >> 4;
    const int tx  = tid & 15;
    const float scaling = 0.08838834764831845f;   // 1/sqrt(128)

    // load + pre-scale Q tile (64 x 128)
    for (int idx = tid; idx < FBM * (HD / 4); idx += 256) {
        int r  = idx >> 5;                  // HD/4 == 32
        int c4 = idx & 31;
        float4 v = *(const float4*)(q + ((long)(q0 + r) * B_SZ + b) * P_DIM + h * HD + c4 * 4);
        float* d = Qs + r * FSTR + c4 * 4;
        d[0] = v.x * scaling; d[1] = v.y * scaling;
        d[2] = v.z * scaling; d[3] = v.w * scaling;
    }

    float o_acc[4][8] = {};
    float m_run[4], l_run[4];
#pragma unroll
    for (int i = 0; i < 4; i++) { m_run[i] = -1e30f; l_run[i] = 0.0f; }

    const int nkb = qb + 1;                 // causal: blocks 0..qb
    for (int jb = 0; jb < nkb; jb++) {
        __syncthreads();                    // protect Ks/Vs/Ss reuse (and Q on first iter)
        const int j0 = jb * FBN;
        for (int idx = tid; idx < FBN * (HD / 4); idx += 256) {
            int r  = idx >> 5;
            int c4 = idx & 31;
            long base = ((long)(j0 + r) * B_SZ + b) * (2 * P_DIM) + h * HD + c4 * 4;
            float4 kk4 = *(const float4*)(kv + base);
            float4 vv4 = *(const float4*)(kv + base + P_DIM);
            *(float4*)(Ks + r * FSTR + c4 * 4) = kk4;
            *(float4*)(Vs + r * FSTR + c4 * 4) = vv4;
        }
        __syncthreads();

        // S = (Q*scale) K^T  : 4x4 per thread
        float s[4][4] = {};
#pragma unroll 8
        for (int kk = 0; kk < HD; kk++) {
            float qr[4], kr[4];
#pragma unroll
            for (int i = 0; i < 4; i++) qr[i] = Qs[(ty * 4 + i) * FSTR + kk];
#pragma unroll
            for (int j = 0; j < 4; j++) kr[j] = Ks[(tx * 4 + j) * FSTR + kk];
#pragma unroll
            for (int i = 0; i < 4; i++)
#pragma unroll
                for (int j = 0; j < 4; j++)
                    s[i][j] += qr[i] * kr[j];
        }

        if (jb == qb) {                     // diagonal block: causal mask
#pragma unroll
            for (int i = 0; i < 4; i++)
#pragma unroll
                for (int j = 0; j < 4; j++)
                    if (j0 + tx * 4 + j > q0 + ty * 4 + i) s[i][j] = -1e30f;
        }

        // online softmax
        float mnew[4];
#pragma unroll
        for (int i = 0; i < 4; i++)
            mnew[i] = fmaxf(fmaxf(s[i][0], s[i][1]), fmaxf(s[i][2], s[i][3]));
#pragma unroll
        for (int off = 8; off >= 1; off >>= 1)
#pragma unroll
            for (int i = 0; i < 4; i++)
                mnew[i] = fmaxf(mnew[i], __shfl_xor_sync(0xffffffffu, mnew[i], off));

        float p[4][4], lsum[4], resc[4];
#pragma unroll
        for (int i = 0; i < 4; i++) {
            float m2 = fmaxf(m_run[i], mnew[i]);
            resc[i]  = __expf(m_run[i] - m2);
            m_run[i] = m2;
            lsum[i]  = 0.0f;
#pragma unroll
            for (int j = 0; j < 4; j++) {
                p[i][j] = __expf(s[i][j] - m2);
                lsum[i] += p[i][j];
            }
        }
#pragma unroll
        for (int off = 8; off >= 1; off >>= 1)
#pragma unroll
            for (int i = 0; i < 4; i++)
                lsum[i] += __shfl_xor_sync(0xffffffffu, lsum[i], off);
#pragma unroll
        for (int i = 0; i < 4; i++)
            l_run[i] = l_run[i] * resc[i] + lsum[i];

        // share P, rescale O
#pragma unroll
        for (int i = 0; i < 4; i++)
#pragma unroll
            for (int j = 0; j < 4; j++)
                Ss[(ty * 4 + i) * SSTR + tx * 4 + j] = p[i][j];
#pragma unroll
        for (int i = 0; i < 4; i++)
#pragma unroll
            for (int jj = 0; jj < 8; jj++)
                o_acc[i][jj] *= resc[i];
        __syncthreads();

        // O += P * V   : 4 rows x 8 cols per thread
#pragma unroll 4
        for (int kk = 0; kk < FBN; kk++) {
            float4 v0 = *(const float4*)(Vs + kk * FSTR + tx * 8);
            float4 v1 = *(const float4*)(Vs + kk * FSTR + tx * 8 + 4);
            float vv[8] = { v0.x, v0.y, v0.z, v0.w, v1.x, v1.y, v1.z, v1.w };
#pragma unroll
            for (int i = 0; i < 4; i++) {
                float pr = Ss[(ty * 4 + i) * SSTR + kk];
#pragma unroll
                for (int jj = 0; jj < 8; jj++)
                    o_acc[i][jj] += pr * vv[jj];
            }
        }
    }

    // epilogue: normalize, store
#pragma unroll
    for (int i = 0; i < 4; i++) {
        float inv = 1.0f / l_run[i];
        int   r   = q0 + ty * 4 + i;
        float* d  = o + ((long)r * B_SZ + b) * P_DIM + h * HD + tx * 8;
        float4 w0 = make_float4(o_acc[i][0] * inv, o_acc[i][1] * inv,
                                o_acc[i][2] * inv, o_acc[i][3] * inv);
        float4 w1 = make_float4(o_acc[i][4] * inv, o_acc[i][5] * inv,
                                o_acc[i][6] * inv, o_acc[i][7] * inv);
        *(float4*)(d)     = w0;
        *(float4*)(d + 4) = w1;
    }
}

// ============================================================================
// rezero residual + LayerNorm : one block (256 thr) per row, P=1024 (4/thread)
// ============================================================================
__global__ void __launch_bounds__(256)
rezero_ln(const float* __restrict__ att, const float* __restrict__ res,
          const float* __restrict__ alpha, const float* __restrict__ w,
          const float* __restrict__ bia, float* __restrict__ out)
{
    __shared__ float red[8];
    const int row = blockIdx.x;
    const int tid = threadIdx.x;
    const int lane = tid & 31, warp = tid >> 5;
    const float a = alpha[0];

    float4 x4 = *(const float4*)(att + (long)row * P_DIM + tid * 4);
    float4 r4 = *(const float4*)(res + (long)row * P_DIM + tid * 4);
    float v[4] = { a * x4.x + r4.x, a * x4.y + r4.y,
                   a * x4.z + r4.z, a * x4.w + r4.w };

    float s = v[0] + v[1] + v[2] + v[3];
#pragma unroll
    for (int off = 16; off >= 1; off >>= 1) s += __shfl_xor_sync(0xffffffffu, s, off);
    if (lane == 0) red[warp] = s;
    __syncthreads();
    s = red[0] + red[1] + red[2] + red[3] + red[4] + red[5] + red[6] + red[7];
    const float mu = s * (1.0f / P_DIM);

    float d0 = v[0] - mu, d1 = v[1] - mu, d2 = v[2] - mu, d3 = v[3] - mu;
    float ss = d0 * d0 + d1 * d1 + d2 * d2 + d3 * d3;
#pragma unroll
    for (int off = 16; off >= 1; off >>= 1) ss += __shfl_xor_sync(0xffffffffu, ss, off);
    __syncthreads();
    if (lane == 0) red[warp] = ss;
    __syncthreads();
    ss = red[0] + red[1] + red[2] + red[3] + red[4] + red[5] + red[6] + red[7];
    const float inv = rsqrtf(ss * (1.0f / P_DIM) + LN_EPS);

    float4 w4 = *(const float4*)(w  + tid * 4);
    float4 b4 = *(const float4*)(bia + tid * 4);
    float4 o4 = make_float4(d0 * inv * w4.x + b4.x, d1 * inv * w4.y + b4.y,
                            d2 * inv * w4.z + b4.z, d3 * inv * w4.w + b4.w);
    *(float4*)(out + (long)row * P_DIM + tid * 4) = o4;
}

// ============================================================================
// launch
// ============================================================================
extern "C" void kernel_launch(void* const* d_in, const int* in_sizes, int n_in,
                              void* d_out, int out_size)
{
    const float* input = (const float*)d_in[0];
    // d_in[1] = attn_mask (pure causal -1e9; handled analytically)
    const float* W1    = (const float*)d_in[2];
    const float* W2    = (const float*)d_in[3];
    const float* W3    = (const float*)d_in[4];
    const float* alpha = (const float*)d_in[5];
    const float* ln_w  = (const float*)d_in[6];
    const float* ln_b  = (const float*)d_in[7];
    float* out = (float*)d_out;

    float *q, *kv, *att, *oln;
    cudaGetSymbolAddress((void**)&q,   g_q);
    cudaGetSymbolAddress((void**)&kv,  g_kv);
    cudaGetSymbolAddress((void**)&att, g_att);
    cudaGetSymbolAddress((void**)&oln, g_oln);

    const int smem_flash = (3 * FBM * FSTR + FBM * SSTR) * (int)sizeof(float); // 118784 B
    cudaFuncSetAttribute(flash_attn, cudaFuncAttributeMaxDynamicSharedMemorySize, smem_flash);

    // 1) q = input * W1^T        [8192,2048] x [1024,2048]^T
    sgemm_abt<<<dim3(P_DIM / GBN, M_ROWS / GBM), 256>>>(input, W1, q, M_ROWS, P_DIM, D_INF);
    // 2) kv = q * W2^T           [8192,1024] x [2048,1024]^T
    sgemm_abt<<<dim3(2 * P_DIM / GBN, M_ROWS / GBM), 256>>>(q, W2, kv, M_ROWS, 2 * P_DIM, P_DIM);
    // 3) causal flash attention
    flash_attn<<<dim3(L_SEQ / FBM, B_SZ * H_HEADS), 256, smem_flash>>>(q, kv, att);
    // 4) rezero + layernorm
    rezero_ln<<<M_ROWS, 256>>>(att, q, alpha, ln_w, ln_b, oln);
    // 5) out = oln * W3^T        [8192,1024] x [2048,1024]^T
    sgemm_abt<<<dim3(D_OUTF / GBN, M_ROWS / GBM), 256>>>(oln, W3, out, M_ROWS, D_OUTF, P_DIM);
}

// round 3
// speedup vs baseline: 1.1066x; 1.1066x over previous
#include <cuda_runtime.h>
#include <math.h>
#include <stdint.h>

// ---------------- problem constants ----------------
#define L_SEQ   2048
#define B_SZ    4
#define D_INF   2048
#define D_OUTF  2048
#define P_DIM   1024
#define H_HEADS 8
#define HD      128
#define M_ROWS  (L_SEQ * B_SZ)        // 8192
#define LN_EPS  1e-5f

// ---------------- scratch (device globals; no allocation allowed) ----------------
__device__ float g_q  [M_ROWS * P_DIM];        // 32 MB
__device__ float g_kv [M_ROWS * 2 * P_DIM];    // 64 MB
__device__ float g_att[M_ROWS * P_DIM];        // 32 MB
__device__ float g_oln[M_ROWS * P_DIM];        // 32 MB

// ============================================================================
// 3xTF32 tensor-core GEMM:  C[M,N] = A[M,K] * B[N,K]^T
// Block 128x128x32, 256 threads (8 warps), warp tile 64x32 (4x4 m16n8k8 mmas).
// A row-major + B[N,K] row-major == B col-major [K,N] -> mma row.col directly.
// Each fp32 value split a = a_hi + a_lo (both tf32); D += Ahi*Blo + Alo*Bhi + Ahi*Bhi.
// ============================================================================
#define TBM 128
#define TBN 128
#define TBK 32
#define TSTR 36           // smem row stride (floats): 4m+k mod 32 distinct -> conflict-free

__device__ __forceinline__ float f2tf32(float x) {
    uint32_t u;
    asm("cvt.rna.tf32.f32 %0, %1;" : "=r"(u) : "f"(x));
    return __uint_as_float(u);
}

__device__ __forceinline__ void mma_tf32(float c[4],
                                         uint32_t a0, uint32_t a1, uint32_t a2, uint32_t a3,
                                         uint32_t b0, uint32_t b1)
{
    asm volatile(
        "mma.sync.aligned.m16n8k8.row.col.f32.tf32.tf32.f32 "
        "{%0,%1,%2,%3}, {%4,%5,%6,%7}, {%8,%9}, {%0,%1,%2,%3};"
        : "+f"(c[0]), "+f"(c[1]), "+f"(c[2]), "+f"(c[3])
        : "r"(a0), "r"(a1), "r"(a2), "r"(a3), "r"(b0), "r"(b1));
}

__global__ void __launch_bounds__(256)
gemm_tf32x3(const float* __restrict__ A, const float* __restrict__ B,
            float* __restrict__ C, int M, int N, int K)
{
    extern __shared__ float sm[];
    float* sAhi = sm;                    // 128*36
    float* sAlo = sAhi + TBM * TSTR;
    float* sBhi = sAlo + TBM * TSTR;
    float* sBlo = sBhi + TBN * TSTR;

    const int tid  = threadIdx.x;
    const int r0   = blockIdx.y * TBM;
    const int c0   = blockIdx.x * TBN;
    const int warp = tid >> 5;
    const int lane = tid & 31;
    const int wm   = warp & 1;           // 2 warps along M
    const int wn   = warp >> 1;          // 4 warps along N
    const int lq   = lane >> 2;          // 0..7
    const int lr   = lane & 3;           // 0..3

    float acc[4][4][4];
#pragma unroll
    for (int i = 0; i < 4; i++)
#pragma unroll
        for (int j = 0; j < 4; j++)
#pragma unroll
            for (int v = 0; v < 4; v++) acc[i][j][v] = 0.0f;

    for (int k0 = 0; k0 < K; k0 += TBK) {
        // ---- load A/B tiles, split into tf32 hi/lo at store time ----
#pragma unroll
        for (int p = 0; p < 4; p++) {
            int idx = tid + p * 256;                 // 0..1023
            int row = idx >> 3;                      // 0..127
            int cc  = (idx & 7) << 2;                // 0,4,...,28
            float4 a = *(const float4*)(A + (long)(r0 + row) * K + k0 + cc);
            float4 ah = make_float4(f2tf32(a.x), f2tf32(a.y), f2tf32(a.z), f2tf32(a.w));
            float4 al = make_float4(f2tf32(a.x - ah.x), f2tf32(a.y - ah.y),
                                    f2tf32(a.z - ah.z), f2tf32(a.w - ah.w));
            *(float4*)(sAhi + row * TSTR + cc) = ah;
            *(float4*)(sAlo + row * TSTR + cc) = al;

            float4 b = *(const float4*)(B + (long)(c0 + row) * K + k0 + cc);
            float4 bh = make_float4(f2tf32(b.x), f2tf32(b.y), f2tf32(b.z), f2tf32(b.w));
            float4 bl = make_float4(f2tf32(b.x - bh.x), f2tf32(b.y - bh.y),
                                    f2tf32(b.z - bh.z), f2tf32(b.w - bh.w));
            *(float4*)(sBhi + row * TSTR + cc) = bh;
            *(float4*)(sBlo + row * TSTR + cc) = bl;
        }
        __syncthreads();

#pragma unroll
        for (int kk = 0; kk < TBK; kk += 8) {
            const int kA = kk + lr;
            uint32_t Ahi[4][4], Alo[4][4], Bhi[4][2], Blo[4][2];
#pragma unroll
            for (int mi = 0; mi < 4; mi++) {
                int ar = wm * 64 + mi * 16 + lq;
                Ahi[mi][0] = __float_as_uint(sAhi[ar * TSTR + kA]);
                Ahi[mi][1] = __float_as_uint(sAhi[(ar + 8) * TSTR + kA]);
                Ahi[mi][2] = __float_as_uint(sAhi[ar * TSTR + kA + 4]);
                Ahi[mi][3] = __float_as_uint(sAhi[(ar + 8) * TSTR + kA + 4]);
                Alo[mi][0] = __float_as_uint(sAlo[ar * TSTR + kA]);
                Alo[mi][1] = __float_as_uint(sAlo[(ar + 8) * TSTR + kA]);
                Alo[mi][2] = __float_as_uint(sAlo[ar * TSTR + kA + 4]);
                Alo[mi][3] = __float_as_uint(sAlo[(ar + 8) * TSTR + kA + 4]);
            }
#pragma unroll
            for (int nj = 0; nj < 4; nj++) {
                int bc = wn * 32 + nj * 8 + lq;
                Bhi[nj][0] = __float_as_uint(sBhi[bc * TSTR + kA]);
                Bhi[nj][1] = __float_as_uint(sBhi[bc * TSTR + kA + 4]);
                Blo[nj][0] = __float_as_uint(sBlo[bc * TSTR + kA]);
                Blo[nj][1] = __float_as_uint(sBlo[bc * TSTR + kA + 4]);
            }
#pragma unroll
            for (int mi = 0; mi < 4; mi++)
#pragma unroll
                for (int nj = 0; nj < 4; nj++) {
                    mma_tf32(acc[mi][nj], Ahi[mi][0], Ahi[mi][1], Ahi[mi][2], Ahi[mi][3],
                             Blo[nj][0], Blo[nj][1]);
                    mma_tf32(acc[mi][nj], Alo[mi][0], Alo[mi][1], Alo[mi][2], Alo[mi][3],
                             Bhi[nj][0], Bhi[nj][1]);
                    mma_tf32(acc[mi][nj], Ahi[mi][0], Ahi[mi][1], Ahi[mi][2], Ahi[mi][3],
                             Bhi[nj][0], Bhi[nj][1]);
                }
        }
        __syncthreads();
    }

    // ---- epilogue ----
#pragma unroll
    for (int mi = 0; mi < 4; mi++) {
#pragma unroll
        for (int nj = 0; nj < 4; nj++) {
            int row = r0 + wm * 64 + mi * 16 + lq;
            int col = c0 + wn * 32 + nj * 8 + lr * 2;
            float2 v0 = make_float2(acc[mi][nj][0], acc[mi][nj][1]);
            float2 v1 = make_float2(acc[mi][nj][2], acc[mi][nj][3]);
            *(float2*)(C + (long)row * N + col)       = v0;
            *(float2*)(C + (long)(row + 8) * N + col) = v1;
        }
    }
}

// ============================================================================
// Causal flash attention, fp32 (unchanged this round).
// ============================================================================
#define FBM  64
#define FBN  64
#define FSTR (HD + 4)
#define SSTR (FBN + 4)

__global__ void __launch_bounds__(256)
flash_attn(const float* __restrict__ q, const float* __restrict__ kv,
           float* __restrict__ o)
{
    extern __shared__ float sm[];
    float* Qs = sm;
    float* Ks = Qs + FBM * FSTR;
    float* Vs = Ks + FBN * FSTR;
    float* Ss = Vs + FBN * FSTR;

    const int tid = threadIdx.x;
    const int qb  = blockIdx.x;
    const int n   = blockIdx.y;
    const int b   = n >> 3;
    const int h   = n & 7;
    const int q0  = qb * FBM;
    const int ty  = tid >> 4;
    const int tx  = tid & 15;
    const float scaling = 0.08838834764831845f;

    for (int idx = tid; idx < FBM * (HD / 4); idx += 256) {
        int r  = idx >> 5;
        int c4 = idx & 31;
        float4 v = *(const float4*)(q + ((long)(q0 + r) * B_SZ + b) * P_DIM + h * HD + c4 * 4);
        float* d = Qs + r * FSTR + c4 * 4;
        d[0] = v.x * scaling; d[1] = v.y * scaling;
        d[2] = v.z * scaling; d[3] = v.w * scaling;
    }

    float o_acc[4][8] = {};
    float m_run[4], l_run[4];
#pragma unroll
    for (int i = 0; i < 4; i++) { m_run[i] = -1e30f; l_run[i] = 0.0f; }

    const int nkb = qb + 1;
    for (int jb = 0; jb < nkb; jb++) {
        __syncthreads();
        const int j0 = jb * FBN;
        for (int idx = tid; idx < FBN * (HD / 4); idx += 256) {
            int r  = idx >> 5;
            int c4 = idx & 31;
            long base = ((long)(j0 + r) * B_SZ + b) * (2 * P_DIM) + h * HD + c4 * 4;
            float4 kk4 = *(const float4*)(kv + base);
            float4 vv4 = *(const float4*)(kv + base + P_DIM);
            *(float4*)(Ks + r * FSTR + c4 * 4) = kk4;
            *(float4*)(Vs + r * FSTR + c4 * 4) = vv4;
        }
        __syncthreads();

        float s[4][4] = {};
#pragma unroll 8
        for (int kk = 0; kk < HD; kk++) {
            float qr[4], kr[4];
#pragma unroll
            for (int i = 0; i < 4; i++) qr[i] = Qs[(ty * 4 + i) * FSTR + kk];
#pragma unroll
            for (int j = 0; j < 4; j++) kr[j] = Ks[(tx * 4 + j) * FSTR + kk];
#pragma unroll
            for (int i = 0; i < 4; i++)
#pragma unroll
                for (int j = 0; j < 4; j++)
                    s[i][j] += qr[i] * kr[j];
        }

        if (jb == qb) {
#pragma unroll
            for (int i = 0; i < 4; i++)
#pragma unroll
                for (int j = 0; j < 4; j++)
                    if (j0 + tx * 4 + j > q0 + ty * 4 + i) s[i][j] = -1e30f;
        }

        float mnew[4];
#pragma unroll
        for (int i = 0; i < 4; i++)
            mnew[i] = fmaxf(fmaxf(s[i][0], s[i][1]), fmaxf(s[i][2], s[i][3]));
#pragma unroll
        for (int off = 8; off >= 1; off >>= 1)
#pragma unroll
            for (int i = 0; i < 4; i++)
                mnew[i] = fmaxf(mnew[i], __shfl_xor_sync(0xffffffffu, mnew[i], off));

        float p[4][4], lsum[4], resc[4];
#pragma unroll
        for (int i = 0; i < 4; i++) {
            float m2 = fmaxf(m_run[i], mnew[i]);
            resc[i]  = __expf(m_run[i] - m2);
            m_run[i] = m2;
            lsum[i]  = 0.0f;
#pragma unroll
            for (int j = 0; j < 4; j++) {
                p[i][j] = __expf(s[i][j] - m2);
                lsum[i] += p[i][j];
            }
        }
#pragma unroll
        for (int off = 8; off >= 1; off >>= 1)
#pragma unroll
            for (int i = 0; i < 4; i++)
                lsum[i] += __shfl_xor_sync(0xffffffffu, lsum[i], off);
#pragma unroll
        for (int i = 0; i < 4; i++)
            l_run[i] = l_run[i] * resc[i] + lsum[i];

#pragma unroll
        for (int i = 0; i < 4; i++)
#pragma unroll
            for (int j = 0; j < 4; j++)
                Ss[(ty * 4 + i) * SSTR + tx * 4 + j] = p[i][j];
#pragma unroll
        for (int i = 0; i < 4; i++)
#pragma unroll
            for (int jj = 0; jj < 8; jj++)
                o_acc[i][jj] *= resc[i];
        __syncthreads();

#pragma unroll 4
        for (int kk = 0; kk < FBN; kk++) {
            float4 v0 = *(const float4*)(Vs + kk * FSTR + tx * 8);
            float4 v1 = *(const float4*)(Vs + kk * FSTR + tx * 8 + 4);
            float vv[8] = { v0.x, v0.y, v0.z, v0.w, v1.x, v1.y, v1.z, v1.w };
#pragma unroll
            for (int i = 0; i < 4; i++) {
                float pr = Ss[(ty * 4 + i) * SSTR + kk];
#pragma unroll
                for (int jj = 0; jj < 8; jj++)
                    o_acc[i][jj] += pr * vv[jj];
            }
        }
    }

#pragma unroll
    for (int i = 0; i < 4; i++) {
        float inv = 1.0f / l_run[i];
        int   r   = q0 + ty * 4 + i;
        float* d  = o + ((long)r * B_SZ + b) * P_DIM + h * HD + tx * 8;
        float4 w0 = make_float4(o_acc[i][0] * inv, o_acc[i][1] * inv,
                                o_acc[i][2] * inv, o_acc[i][3] * inv);
        float4 w1 = make_float4(o_acc[i][4] * inv, o_acc[i][5] * inv,
                                o_acc[i][6] * inv, o_acc[i][7] * inv);
        *(float4*)(d)     = w0;
        *(float4*)(d + 4) = w1;
    }
}

// ============================================================================
// rezero residual + LayerNorm (unchanged)
// ============================================================================
__global__ void __launch_bounds__(256)
rezero_ln(const float* __restrict__ att, const float* __restrict__ res,
          const float* __restrict__ alpha, const float* __restrict__ w,
          const float* __restrict__ bia, float* __restrict__ out)
{
    __shared__ float red[8];
    const int row = blockIdx.x;
    const int tid = threadIdx.x;
    const int lane = tid & 31, warp = tid >> 5;
    const float a = alpha[0];

    float4 x4 = *(const float4*)(att + (long)row * P_DIM + tid * 4);
    float4 r4 = *(const float4*)(res + (long)row * P_DIM + tid * 4);
    float v[4] = { a * x4.x + r4.x, a * x4.y + r4.y,
                   a * x4.z + r4.z, a * x4.w + r4.w };

    float s = v[0] + v[1] + v[2] + v[3];
#pragma unroll
    for (int off = 16; off >= 1; off >>= 1) s += __shfl_xor_sync(0xffffffffu, s, off);
    if (lane == 0) red[warp] = s;
    __syncthreads();
    s = red[0] + red[1] + red[2] + red[3] + red[4] + red[5] + red[6] + red[7];
    const float mu = s * (1.0f / P_DIM);

    float d0 = v[0] - mu, d1 = v[1] - mu, d2 = v[2] - mu, d3 = v[3] - mu;
    float ss = d0 * d0 + d1 * d1 + d2 * d2 + d3 * d3;
#pragma unroll
    for (int off = 16; off >= 1; off >>= 1) ss += __shfl_xor_sync(0xffffffffu, ss, off);
    __syncthreads();
    if (lane == 0) red[warp] = ss;
    __syncthreads();
    ss = red[0] + red[1] + red[2] + red[3] + red[4] + red[5] + red[6] + red[7];
    const float inv = rsqrtf(ss * (1.0f / P_DIM) + LN_EPS);

    float4 w4 = *(const float4*)(w  + tid * 4);
    float4 b4 = *(const float4*)(bia + tid * 4);
    float4 o4 = make_float4(d0 * inv * w4.x + b4.x, d1 * inv * w4.y + b4.y,
                            d2 * inv * w4.z + b4.z, d3 * inv * w4.w + b4.w);
    *(float4*)(out + (long)row * P_DIM + tid * 4) = o4;
}

// ============================================================================
// launch
// ============================================================================
extern "C" void kernel_launch(void* const* d_in, const int* in_sizes, int n_in,
                              void* d_out, int out_size)
{
    const float* input = (const float*)d_in[0];
    const float* W1    = (const float*)d_in[2];
    const float* W2    = (const float*)d_in[3];
    const float* W3    = (const float*)d_in[4];
    const float* alpha = (const float*)d_in[5];
    const float* ln_w  = (const float*)d_in[6];
    const float* ln_b  = (const float*)d_in[7];
    float* out = (float*)d_out;

    float *q, *kv, *att, *oln;
    cudaGetSymbolAddress((void**)&q,   g_q);
    cudaGetSymbolAddress((void**)&kv,  g_kv);
    cudaGetSymbolAddress((void**)&att, g_att);
    cudaGetSymbolAddress((void**)&oln, g_oln);

    const int smem_gemm  = 4 * TBM * TSTR * (int)sizeof(float);                 // 73728 B
    const int smem_flash = (3 * FBM * FSTR + FBM * SSTR) * (int)sizeof(float);  // 118784 B
    cudaFuncSetAttribute(gemm_tf32x3, cudaFuncAttributeMaxDynamicSharedMemorySize, smem_gemm);
    cudaFuncSetAttribute(flash_attn,  cudaFuncAttributeMaxDynamicSharedMemorySize, smem_flash);

    // 1) q = input * W1^T
    gemm_tf32x3<<<dim3(P_DIM / TBN, M_ROWS / TBM), 256, smem_gemm>>>(input, W1, q, M_ROWS, P_DIM, D_INF);
    // 2) kv = q * W2^T
    gemm_tf32x3<<<dim3(2 * P_DIM / TBN, M_ROWS / TBM), 256, smem_gemm>>>(q, W2, kv, M_ROWS, 2 * P_DIM, P_DIM);
    // 3) causal flash attention
    flash_attn<<<dim3(L_SEQ / FBM, B_SZ * H_HEADS), 256, smem_flash>>>(q, kv, att);
    // 4) rezero + layernorm
    rezero_ln<<<M_ROWS, 256>>>(att, q, alpha, ln_w, ln_b, oln);
    // 5) out = oln * W3^T
    gemm_tf32x3<<<dim3(D_OUTF / TBN, M_ROWS / TBM), 256, smem_gemm>>>(oln, W3, out, M_ROWS, D_OUTF, P_DIM);
}

// round 11
// speedup vs baseline: 3.0331x; 2.7408x over previous
#include <cuda_runtime.h>
#include <cuda_bf16.h>
#include <math.h>
#include <stdint.h>

// ---------------- problem constants ----------------
#define L_SEQ   2048
#define B_SZ    4
#define D_INF   2048
#define D_OUTF  2048
#define P_DIM   1024
#define H_HEADS 8
#define HD      128
#define M_ROWS  (L_SEQ * B_SZ)        // 8192
#define LN_EPS  1e-5f

// ---------------- scratch (device globals; no allocation allowed) ----------------
__device__ float g_q  [M_ROWS * P_DIM];
__device__ float g_kv [M_ROWS * 2 * P_DIM];
__device__ float g_att[M_ROWS * P_DIM];
__device__ float g_oln[M_ROWS * P_DIM];

// ============================================================================
// helpers
// ============================================================================
__device__ __forceinline__ uint32_t smem_u32(const void* p) {
    uint32_t a;
    asm("{ .reg .u64 t; cvta.to.shared.u64 t, %1; cvt.u32.u64 %0, t; }" : "=r"(a) : "l"(p));
    return a;
}
__device__ __forceinline__ void ldsm_x4(uint32_t* r, uint32_t addr) {
    asm volatile("ldmatrix.sync.aligned.m8n8.x4.shared.b16 {%0,%1,%2,%3}, [%4];"
                 : "=r"(r[0]), "=r"(r[1]), "=r"(r[2]), "=r"(r[3]) : "r"(addr));
}
__device__ __forceinline__ void ldsm_x2(uint32_t* r, uint32_t addr) {
    asm volatile("ldmatrix.sync.aligned.m8n8.x2.shared.b16 {%0,%1}, [%2];"
                 : "=r"(r[0]), "=r"(r[1]) : "r"(addr));
}
__device__ __forceinline__ void ldsm_x2_t(uint32_t* r, uint32_t addr) {
    asm volatile("ldmatrix.sync.aligned.m8n8.x2.trans.shared.b16 {%0,%1}, [%2];"
                 : "=r"(r[0]), "=r"(r[1]) : "r"(addr));
}
__device__ __forceinline__ void mma_bf16(float* c, const uint32_t* a, const uint32_t* b) {
    asm volatile(
        "mma.sync.aligned.m16n8k16.row.col.f32.bf16.bf16.f32 "
        "{%0,%1,%2,%3}, {%4,%5,%6,%7}, {%8,%9}, {%0,%1,%2,%3};"
        : "+f"(c[0]), "+f"(c[1]), "+f"(c[2]), "+f"(c[3])
        : "r"(a[0]), "r"(a[1]), "r"(a[2]), "r"(a[3]), "r"(b[0]), "r"(b[1]));
}
__device__ __forceinline__ uint32_t pk_bf2(float x, float y) {
    __nv_bfloat162 t = __halves2bfloat162(__float2bfloat16(x), __float2bfloat16(y));
    return *(uint32_t*)&t;
}

// ============================================================================
// 3xBF16 tensor-core GEMM:  C[M,N] = A[M,K] * B[N,K]^T   (unchanged, audited)
// ============================================================================
#define BBK     32
#define BSTR    40
#define AELEMS  (128 * BSTR)
#define STAGE_H (4 * AELEMS)
#define GB_SMEM (2 * STAGE_H * 2)          // 81920 bytes

__global__ void __launch_bounds__(256)
gemm_bf16x3(const float* __restrict__ A, const float* __restrict__ B,
            float* __restrict__ C, int M, int N, int K)
{
    extern __shared__ char smraw[];
    __nv_bfloat16* smh = (__nv_bfloat16*)smraw;
    const uint32_t sb32 = smem_u32(smraw);

    const int tid  = threadIdx.x;
    const int lane = tid & 31;
    const int wid  = tid >> 5;
    const int r0   = blockIdx.y * 128;
    const int c0   = blockIdx.x * 128;
    const int m_base = (wid & 3) * 32;
    const int n_base = (wid >> 2) * 64;

    const int lrow = tid >> 1;
    const int lcg  = (tid & 1) * 16;
    const float* Ag = A + (long)(r0 + lrow) * K + lcg;
    const float* Bg = B + (long)(c0 + lrow) * K + lcg;

    float4 ra[4], rb[4];
    float acc[2][8][4] = {};

    auto LOAD = [&](int c) {
        const float* ap = Ag + c * BBK;
        const float* bp = Bg + c * BBK;
#pragma unroll
        for (int i = 0; i < 4; i++) {
            ra[i] = *(const float4*)(ap + 4 * i);
            rb[i] = *(const float4*)(bp + 4 * i);
        }
    };
    auto STORE = [&](int s) {
        __nv_bfloat16* dA = smh + s * STAGE_H + lrow * BSTR + lcg;
        __nv_bfloat16* dB = dA + 2 * AELEMS;
#pragma unroll
        for (int i = 0; i < 4; i++) {
            float4 v = ra[i];
            __nv_bfloat16 h0 = __float2bfloat16(v.x), h1 = __float2bfloat16(v.y);
            __nv_bfloat16 h2 = __float2bfloat16(v.z), h3 = __float2bfloat16(v.w);
            __nv_bfloat16 l0 = __float2bfloat16(v.x - __bfloat162float(h0));
            __nv_bfloat16 l1 = __float2bfloat16(v.y - __bfloat162float(h1));
            __nv_bfloat16 l2 = __float2bfloat16(v.z - __bfloat162float(h2));
            __nv_bfloat16 l3 = __float2bfloat16(v.w - __bfloat162float(h3));
            *(__nv_bfloat162*)(dA + 4 * i)              = __halves2bfloat162(h0, h1);
            *(__nv_bfloat162*)(dA + 4 * i + 2)          = __halves2bfloat162(h2, h3);
            *(__nv_bfloat162*)(dA + AELEMS + 4 * i)     = __halves2bfloat162(l0, l1);
            *(__nv_bfloat162*)(dA + AELEMS + 4 * i + 2) = __halves2bfloat162(l2, l3);

            float4 w = rb[i];
            __nv_bfloat16 g0 = __float2bfloat16(w.x), g1 = __float2bfloat16(w.y);
            __nv_bfloat16 g2 = __float2bfloat16(w.z), g3 = __float2bfloat16(w.w);
            __nv_bfloat16 m0 = __float2bfloat16(w.x - __bfloat162float(g0));
            __nv_bfloat16 m1 = __float2bfloat16(w.y - __bfloat162float(g1));
            __nv_bfloat16 m2 = __float2bfloat16(w.z - __bfloat162float(g2));
            __nv_bfloat16 m3 = __float2bfloat16(w.w - __bfloat162float(g3));
            *(__nv_bfloat162*)(dB + 4 * i)              = __halves2bfloat162(g0, g1);
            *(__nv_bfloat162*)(dB + 4 * i + 2)          = __halves2bfloat162(g2, g3);
            *(__nv_bfloat162*)(dB + AELEMS + 4 * i)     = __halves2bfloat162(m0, m1);
            *(__nv_bfloat162*)(dB + AELEMS + 4 * i + 2) = __halves2bfloat162(m2, m3);
        }
    };

    const int arow = m_base + (lane & 15);
    const int akh  = (lane >> 4) << 3;
    const int brow = n_base + (lane & 7);
    const int bkh  = ((lane >> 3) & 1) << 3;

    auto COMPUTE = [&](int s) {
        const uint32_t stA = sb32 + (uint32_t)(s * STAGE_H) * 2;
        const uint32_t stB = stA + (uint32_t)(2 * AELEMS) * 2;
#pragma unroll
        for (int ks = 0; ks < BBK; ks += 16) {
            uint32_t Ah[2][4], Al[2][4];
#pragma unroll
            for (int mt = 0; mt < 2; mt++) {
                uint32_t addr = stA + (uint32_t)((arow + mt * 16) * BSTR + ks + akh) * 2;
                ldsm_x4(Ah[mt], addr);
                ldsm_x4(Al[mt], addr + AELEMS * 2);
            }
#pragma unroll
            for (int ng = 0; ng < 2; ng++) {
                uint32_t Bh[4][2], Bl[4][2];
#pragma unroll
                for (int j = 0; j < 4; j++) {
                    int nt = ng * 4 + j;
                    uint32_t addr = stB + (uint32_t)((brow + nt * 8) * BSTR + ks + bkh) * 2;
                    ldsm_x2(Bh[j], addr);
                    ldsm_x2(Bl[j], addr + AELEMS * 2);
                }
#pragma unroll
                for (int mt = 0; mt < 2; mt++)
#pragma unroll
                    for (int j = 0; j < 4; j++) {
                        float* c = acc[mt][ng * 4 + j];
                        mma_bf16(c, Ah[mt], Bl[j]);
                        mma_bf16(c, Al[mt], Bh[j]);
                        mma_bf16(c, Ah[mt], Bh[j]);
                    }
            }
        }
    };

    const int NC = K / BBK;
    LOAD(0); STORE(0); __syncthreads();
    for (int c = 0; c < NC; c++) {
        const int s = c & 1;
        if (c + 1 < NC) LOAD(c + 1);
        COMPUTE(s);
        if (c + 1 < NC) STORE(s ^ 1);
        __syncthreads();
    }

    const int lq  = lane >> 2;
    const int lr2 = (lane & 3) * 2;
#pragma unroll
    for (int mt = 0; mt < 2; mt++)
#pragma unroll
        for (int nt = 0; nt < 8; nt++) {
            int row = r0 + m_base + mt * 16 + lq;
            int col = c0 + n_base + nt * 8 + lr2;
            *(float2*)(C + (long)row * N + col)       = make_float2(acc[mt][nt][0], acc[mt][nt][1]);
            *(float2*)(C + (long)(row + 8) * N + col) = make_float2(acc[mt][nt][2], acc[mt][nt][3]);
        }
}

// ============================================================================
// bf16-mma causal flash attention.
// Block: 128 q-rows, 8 warps (16 rows each), K-tiles of 64, HD=128.
// QK^T: 3-term hi/lo bf16. P*V: 1-pass bf16 (alpha=0.1 damps output error).
// ============================================================================
#define AQB   128
#define AKB   64
#define QSTR  136
#define FA_QHI   0
#define FA_QLO   (128 * QSTR)
#define FA_KHI   (FA_QLO + 128 * QSTR)
#define FA_KLO   (FA_KHI + 64 * QSTR)
#define FA_V     (FA_KLO + 64 * QSTR)
#define FA_SMEM  ((FA_V + 64 * QSTR) * 2)     // 121856 bytes

__global__ void __launch_bounds__(256, 1)
flash_attn_mma(const float* __restrict__ q, const float* __restrict__ kv,
               float* __restrict__ o)
{
    extern __shared__ char smraw[];
    __nv_bfloat16* smh = (__nv_bfloat16*)smraw;
    const uint32_t sb32 = smem_u32(smraw);

    const int tid  = threadIdx.x;
    const int lane = tid & 31;
    const int wid  = tid >> 5;
    const int qbi  = gridDim.x - 1 - blockIdx.x;   // heavy blocks first
    const int n    = blockIdx.y;
    const int b    = n >> 3;
    const int h    = n & 7;
    const int q0   = qbi * AQB;
    const float scaling = 0.08838834764831845f;    // 1/sqrt(128)

    // ---- load + scale + split Q (128 rows x 128 cols; 2 thr/row x 64 cols) ----
    {
        const int lrow = tid >> 1;                 // 0..127
        const int cb   = (tid & 1) * 64;           // 0 / 64
        const float* qp = q + ((long)(q0 + lrow) * B_SZ + b) * P_DIM + h * HD + cb;
        __nv_bfloat16* dH = smh + FA_QHI + lrow * QSTR + cb;
        __nv_bfloat16* dL = smh + FA_QLO + lrow * QSTR + cb;
#pragma unroll
        for (int i = 0; i < 16; i++) {
            float4 v = *(const float4*)(qp + 4 * i);
            v.x *= scaling; v.y *= scaling; v.z *= scaling; v.w *= scaling;
            __nv_bfloat16 h0 = __float2bfloat16(v.x), h1 = __float2bfloat16(v.y);
            __nv_bfloat16 h2 = __float2bfloat16(v.z), h3 = __float2bfloat16(v.w);
            __nv_bfloat16 l0 = __float2bfloat16(v.x - __bfloat162float(h0));
            __nv_bfloat16 l1 = __float2bfloat16(v.y - __bfloat162float(h1));
            __nv_bfloat16 l2 = __float2bfloat16(v.z - __bfloat162float(h2));
            __nv_bfloat16 l3 = __float2bfloat16(v.w - __bfloat162float(h3));
            *(__nv_bfloat162*)(dH + 4 * i)     = __halves2bfloat162(h0, h1);
            *(__nv_bfloat162*)(dH + 4 * i + 2) = __halves2bfloat162(h2, h3);
            *(__nv_bfloat162*)(dL + 4 * i)     = __halves2bfloat162(l0, l1);
            *(__nv_bfloat162*)(dL + 4 * i + 2) = __halves2bfloat162(l2, l3);
        }
    }

    const int lq = lane >> 2;
    const int lr = lane & 3;
    float oacc[16][4];
#pragma unroll
    for (int i = 0; i < 16; i++)
#pragma unroll
        for (int j = 0; j < 4; j++) oacc[i][j] = 0.0f;
    float mA = -1e30f, mB = -1e30f, lA = 0.0f, lB = 0.0f;

    const int arow = wid * 16 + (lane & 15);
    const int akh  = (lane >> 4) << 3;
    const int brow = lane & 7;
    const int bkh  = ((lane >> 3) & 1) << 3;

    const int nkb = 2 * qbi + 2;
    for (int jb = 0; jb < nkb; jb++) {
        const int j0 = jb * AKB;
        __syncthreads();                            // prior readers done (and Q ready, iter 0)
        // ---- load K (hi/lo) + V (64 rows x 128 cols; 4 thr/row x 32 cols) ----
        {
            const int lrow = tid >> 2;              // 0..63
            const int cb   = (tid & 3) * 32;        // 0,32,64,96
            long base = ((long)(j0 + lrow) * B_SZ + b) * (2 * P_DIM) + h * HD + cb;
            __nv_bfloat16* dH = smh + FA_KHI + lrow * QSTR + cb;
            __nv_bfloat16* dL = smh + FA_KLO + lrow * QSTR + cb;
            __nv_bfloat16* dV = smh + FA_V   + lrow * QSTR + cb;
#pragma unroll
            for (int i = 0; i < 8; i++) {
                float4 v = *(const float4*)(kv + base + 4 * i);
                __nv_bfloat16 h0 = __float2bfloat16(v.x), h1 = __float2bfloat16(v.y);
                __nv_bfloat16 h2 = __float2bfloat16(v.z), h3 = __float2bfloat16(v.w);
                __nv_bfloat16 l0 = __float2bfloat16(v.x - __bfloat162float(h0));
                __nv_bfloat16 l1 = __float2bfloat16(v.y - __bfloat162float(h1));
                __nv_bfloat16 l2 = __float2bfloat16(v.z - __bfloat162float(h2));
                __nv_bfloat16 l3 = __float2bfloat16(v.w - __bfloat162float(h3));
                *(__nv_bfloat162*)(dH + 4 * i)     = __halves2bfloat162(h0, h1);
                *(__nv_bfloat162*)(dH + 4 * i + 2) = __halves2bfloat162(h2, h3);
                *(__nv_bfloat162*)(dL + 4 * i)     = __halves2bfloat162(l0, l1);
                *(__nv_bfloat162*)(dL + 4 * i + 2) = __halves2bfloat162(l2, l3);

                float4 w = *(const float4*)(kv + base + P_DIM + 4 * i);
                *(__nv_bfloat162*)(dV + 4 * i)     = __halves2bfloat162(__float2bfloat16(w.x), __float2bfloat16(w.y));
                *(__nv_bfloat162*)(dV + 4 * i + 2) = __halves2bfloat162(__float2bfloat16(w.z), __float2bfloat16(w.w));
            }
        }
        __syncthreads();

        // ---- S = Q K^T over HD=128 (8 k-steps), 8 n8-tiles ----
        float sacc[8][4];
#pragma unroll
        for (int i = 0; i < 8; i++)
#pragma unroll
            for (int j = 0; j < 4; j++) sacc[i][j] = 0.0f;

#pragma unroll
        for (int ks = 0; ks < 8; ks++) {
            uint32_t Ah[4], Al[4];
            uint32_t aaddr = sb32 + (uint32_t)(arow * QSTR + ks * 16 + akh) * 2;
            ldsm_x4(Ah, aaddr + FA_QHI * 2);
            ldsm_x4(Al, aaddr + FA_QLO * 2);
#pragma unroll
            for (int nt = 0; nt < 8; nt++) {
                uint32_t Bh[2], Bl[2];
                uint32_t baddr = sb32 + (uint32_t)((nt * 8 + brow) * QSTR + ks * 16 + bkh) * 2;
                ldsm_x2(Bh, baddr + FA_KHI * 2);
                ldsm_x2(Bl, baddr + FA_KLO * 2);
                mma_bf16(sacc[nt], Ah, Bl);
                mma_bf16(sacc[nt], Al, Bh);
                mma_bf16(sacc[nt], Ah, Bh);
            }
        }

        // ---- causal mask (diagonal-overlapping K-blocks only) ----
        if (j0 + AKB - 1 > q0) {
            const int rowA = q0 + wid * 16 + lq;
            const int rowB = rowA + 8;
#pragma unroll
            for (int nt = 0; nt < 8; nt++) {
                int col = j0 + nt * 8 + 2 * lr;
                if (col     > rowA) sacc[nt][0] = -1e30f;
                if (col + 1 > rowA) sacc[nt][1] = -1e30f;
                if (col     > rowB) sacc[nt][2] = -1e30f;
                if (col + 1 > rowB) sacc[nt][3] = -1e30f;
            }
        }

        // ---- online softmax (2 rows per thread; quad reductions) ----
        float nmA = -1e30f, nmB = -1e30f;
#pragma unroll
        for (int nt = 0; nt < 8; nt++) {
            nmA = fmaxf(nmA, fmaxf(sacc[nt][0], sacc[nt][1]));
            nmB = fmaxf(nmB, fmaxf(sacc[nt][2], sacc[nt][3]));
        }
        nmA = fmaxf(nmA, __shfl_xor_sync(0xffffffffu, nmA, 1));
        nmA = fmaxf(nmA, __shfl_xor_sync(0xffffffffu, nmA, 2));
        nmB = fmaxf(nmB, __shfl_xor_sync(0xffffffffu, nmB, 1));
        nmB = fmaxf(nmB, __shfl_xor_sync(0xffffffffu, nmB, 2));

        float m2A = fmaxf(mA, nmA), m2B = fmaxf(mB, nmB);
        float rsA = __expf(mA - m2A), rsB = __expf(mB - m2B);
        mA = m2A; mB = m2B;

        float sumA = 0.0f, sumB = 0.0f;
        uint32_t aP[4][4];
#pragma unroll
        for (int g = 0; g < 4; g++) {
            float p00 = __expf(sacc[2*g][0]   - m2A);
            float p01 = __expf(sacc[2*g][1]   - m2A);
            float p02 = __expf(sacc[2*g][2]   - m2B);
            float p03 = __expf(sacc[2*g][3]   - m2B);
            float p10 = __expf(sacc[2*g+1][0] - m2A);
            float p11 = __expf(sacc[2*g+1][1] - m2A);
            float p12 = __expf(sacc[2*g+1][2] - m2B);
            float p13 = __expf(sacc[2*g+1][3] - m2B);
            sumA += p00 + p01 + p10 + p11;
            sumB += p02 + p03 + p12 + p13;
            aP[g][0] = pk_bf2(p00, p01);
            aP[g][1] = pk_bf2(p02, p03);
            aP[g][2] = pk_bf2(p10, p11);
            aP[g][3] = pk_bf2(p12, p13);
        }
        sumA += __shfl_xor_sync(0xffffffffu, sumA, 1);
        sumA += __shfl_xor_sync(0xffffffffu, sumA, 2);
        sumB += __shfl_xor_sync(0xffffffffu, sumB, 1);
        sumB += __shfl_xor_sync(0xffffffffu, sumB, 2);
        lA = lA * rsA + sumA;
        lB = lB * rsB + sumB;

        // ---- rescale O, then O += P V ----
#pragma unroll
        for (int nt = 0; nt < 16; nt++) {
            oacc[nt][0] *= rsA; oacc[nt][1] *= rsA;
            oacc[nt][2] *= rsB; oacc[nt][3] *= rsB;
        }
#pragma unroll
        for (int g = 0; g < 4; g++) {
#pragma unroll
            for (int nt = 0; nt < 16; nt++) {
                uint32_t Bv[2];
                uint32_t vaddr = sb32 + (uint32_t)(FA_V + (g * 16 + (lane & 15)) * QSTR + nt * 8) * 2;
                ldsm_x2_t(Bv, vaddr);
                mma_bf16(oacc[nt], aP[g], Bv);
            }
        }
    }

    // ---- epilogue: normalize + store ----
    {
        const float iA = 1.0f / lA, iB = 1.0f / lB;
        const int rowA = q0 + wid * 16 + lq;
        const int rowB = rowA + 8;
        float* dA = o + ((long)rowA * B_SZ + b) * P_DIM + h * HD;
        float* dB = o + ((long)rowB * B_SZ + b) * P_DIM + h * HD;
#pragma unroll
        for (int nt = 0; nt < 16; nt++) {
            int col = nt * 8 + 2 * lr;
            *(float2*)(dA + col) = make_float2(oacc[nt][0] * iA, oacc[nt][1] * iA);
            *(float2*)(dB + col) = make_float2(oacc[nt][2] * iB, oacc[nt][3] * iB);
        }
    }
}

// ============================================================================
// rezero residual + LayerNorm (unchanged)
// ============================================================================
__global__ void __launch_bounds__(256)
rezero_ln(const float* __restrict__ att, const float* __restrict__ res,
          const float* __restrict__ alpha, const float* __restrict__ w,
          const float* __restrict__ bia, float* __restrict__ out)
{
    __shared__ float red[8];
    const int row = blockIdx.x;
    const int tid = threadIdx.x;
    const int lane = tid & 31, warp = tid >> 5;
    const float a = alpha[0];

    float4 x4 = *(const float4*)(att + (long)row * P_DIM + tid * 4);
    float4 r4 = *(const float4*)(res + (long)row * P_DIM + tid * 4);
    float v[4] = { a * x4.x + r4.x, a * x4.y + r4.y,
                   a * x4.z + r4.z, a * x4.w + r4.w };

    float s = v[0] + v[1] + v[2] + v[3];
#pragma unroll
    for (int off = 16; off >= 1; off >>= 1) s += __shfl_xor_sync(0xffffffffu, s, off);
    if (lane == 0) red[warp] = s;
    __syncthreads();
    s = red[0] + red[1] + red[2] + red[3] + red[4] + red[5] + red[6] + red[7];
    const float mu = s * (1.0f / P_DIM);

    float d0 = v[0] - mu, d1 = v[1] - mu, d2 = v[2] - mu, d3 = v[3] - mu;
    float ss = d0 * d0 + d1 * d1 + d2 * d2 + d3 * d3;
#pragma unroll
    for (int off = 16; off >= 1; off >>= 1) ss += __shfl_xor_sync(0xffffffffu, ss, off);
    __syncthreads();
    if (lane == 0) red[warp] = ss;
    __syncthreads();
    ss = red[0] + red[1] + red[2] + red[3] + red[4] + red[5] + red[6] + red[7];
    const float inv = rsqrtf(ss * (1.0f / P_DIM) + LN_EPS);

    float4 w4 = *(const float4*)(w  + tid * 4);
    float4 b4 = *(const float4*)(bia + tid * 4);
    float4 o4 = make_float4(d0 * inv * w4.x + b4.x, d1 * inv * w4.y + b4.y,
                            d2 * inv * w4.z + b4.z, d3 * inv * w4.w + b4.w);
    *(float4*)(out + (long)row * P_DIM + tid * 4) = o4;
}

// ============================================================================
// launch
// ============================================================================
extern "C" void kernel_launch(void* const* d_in, const int* in_sizes, int n_in,
                              void* d_out, int out_size)
{
    const float* input = (const float*)d_in[0];
    const float* W1    = (const float*)d_in[2];
    const float* W2    = (const float*)d_in[3];
    const float* W3    = (const float*)d_in[4];
    const float* alpha = (const float*)d_in[5];
    const float* ln_w  = (const float*)d_in[6];
    const float* ln_b  = (const float*)d_in[7];
    float* out = (float*)d_out;

    float *q, *kv, *att, *oln;
    cudaGetSymbolAddress((void**)&q,   g_q);
    cudaGetSymbolAddress((void**)&kv,  g_kv);
    cudaGetSymbolAddress((void**)&att, g_att);
    cudaGetSymbolAddress((void**)&oln, g_oln);

    cudaFuncSetAttribute(gemm_bf16x3,    cudaFuncAttributeMaxDynamicSharedMemorySize, GB_SMEM);
    cudaFuncSetAttribute(flash_attn_mma, cudaFuncAttributeMaxDynamicSharedMemorySize, FA_SMEM);

    // 1) q = input * W1^T
    gemm_bf16x3<<<dim3(P_DIM / 128, M_ROWS / 128), 256, GB_SMEM>>>(input, W1, q, M_ROWS, P_DIM, D_INF);
    // 2) kv = q * W2^T
    gemm_bf16x3<<<dim3(2 * P_DIM / 128, M_ROWS / 128), 256, GB_SMEM>>>(q, W2, kv, M_ROWS, 2 * P_DIM, P_DIM);
    // 3) causal flash attention (bf16 mma)
    flash_attn_mma<<<dim3(L_SEQ / AQB, B_SZ * H_HEADS), 256, FA_SMEM>>>(q, kv, att);
    // 4) rezero + layernorm
    rezero_ln<<<M_ROWS, 256>>>(att, q, alpha, ln_w, ln_b, oln);
    // 5) out = oln * W3^T
    gemm_bf16x3<<<dim3(D_OUTF / 128, M_ROWS / 128), 256, GB_SMEM>>>(oln, W3, out, M_ROWS, D_OUTF, P_DIM);
}

// round 16
// speedup vs baseline: 3.0765x; 1.0143x over previous
#include <cuda_runtime.h>
#include <cuda_bf16.h>
#include <math.h>
#include <stdint.h>

// ---------------- problem constants ----------------
#define L_SEQ   2048
#define B_SZ    4
#define D_INF   2048
#define D_OUTF  2048
#define P_DIM   1024
#define H_HEADS 8
#define HD      128
#define M_ROWS  (L_SEQ * B_SZ)        // 8192
#define LN_EPS  1e-5f

// ---------------- scratch (device globals; no allocation allowed) ----------------
__device__ float g_q  [M_ROWS * P_DIM];
__device__ float g_kv [M_ROWS * 2 * P_DIM];
__device__ float g_att[M_ROWS * P_DIM];
__device__ float g_oln[M_ROWS * P_DIM];

// ============================================================================
// helpers
// ============================================================================
__device__ __forceinline__ uint32_t smem_u32(const void* p) {
    uint32_t a;
    asm("{ .reg .u64 t; cvta.to.shared.u64 t, %1; cvt.u32.u64 %0, t; }" : "=r"(a) : "l"(p));
    return a;
}
__device__ __forceinline__ void ldsm_x4(uint32_t* r, uint32_t addr) {
    asm volatile("ldmatrix.sync.aligned.m8n8.x4.shared.b16 {%0,%1,%2,%3}, [%4];"
                 : "=r"(r[0]), "=r"(r[1]), "=r"(r[2]), "=r"(r[3]) : "r"(addr));
}
__device__ __forceinline__ void ldsm_x4_t(uint32_t* r, uint32_t addr) {
    asm volatile("ldmatrix.sync.aligned.m8n8.x4.trans.shared.b16 {%0,%1,%2,%3}, [%4];"
                 : "=r"(r[0]), "=r"(r[1]), "=r"(r[2]), "=r"(r[3]) : "r"(addr));
}
__device__ __forceinline__ void mma_bf16(float* c, const uint32_t* a, const uint32_t* b) {
    asm volatile(
        "mma.sync.aligned.m16n8k16.row.col.f32.bf16.bf16.f32 "
        "{%0,%1,%2,%3}, {%4,%5,%6,%7}, {%8,%9}, {%0,%1,%2,%3};"
        : "+f"(c[0]), "+f"(c[1]), "+f"(c[2]), "+f"(c[3])
        : "r"(a[0]), "r"(a[1]), "r"(a[2]), "r"(a[3]), "r"(b[0]), "r"(b[1]));
}
__device__ __forceinline__ uint32_t pk_bf2(float x, float y) {
    __nv_bfloat162 t = __halves2bfloat162(__float2bfloat16(x), __float2bfloat16(y));
    return *(uint32_t*)&t;
}

// ============================================================================
// 3xBF16 tensor-core GEMM:  C[M,N] = A[M,K] * B[N,K]^T
// v2: B fragments via ldsm.x4 pair-tiles (same audited idiom as attention).
// ============================================================================
#define BBK     32
#define BSTR    40
#define AELEMS  (128 * BSTR)
#define STAGE_H (4 * AELEMS)
#define GB_SMEM (2 * STAGE_H * 2)          // 81920 bytes

__global__ void __launch_bounds__(256)
gemm_bf16x3(const float* __restrict__ A, const float* __restrict__ B,
            float* __restrict__ C, int M, int N, int K)
{
    extern __shared__ char smraw[];
    __nv_bfloat16* smh = (__nv_bfloat16*)smraw;
    const uint32_t sb32 = smem_u32(smraw);

    const int tid  = threadIdx.x;
    const int lane = tid & 31;
    const int wid  = tid >> 5;
    const int r0   = blockIdx.y * 128;
    const int c0   = blockIdx.x * 128;
    const int m_base = (wid & 3) * 32;
    const int n_base = (wid >> 2) * 64;

    const int lrow = tid >> 1;
    const int lcg  = (tid & 1) * 16;
    const float* Ag = A + (long)(r0 + lrow) * K + lcg;
    const float* Bg = B + (long)(c0 + lrow) * K + lcg;

    float4 ra[4], rb[4];
    float acc[2][8][4] = {};

    auto LOAD = [&](int c) {
        const float* ap = Ag + c * BBK;
        const float* bp = Bg + c * BBK;
#pragma unroll
        for (int i = 0; i < 4; i++) {
            ra[i] = *(const float4*)(ap + 4 * i);
            rb[i] = *(const float4*)(bp + 4 * i);
        }
    };
    auto STORE = [&](int s) {
        __nv_bfloat16* dA = smh + s * STAGE_H + lrow * BSTR + lcg;
        __nv_bfloat16* dB = dA + 2 * AELEMS;
#pragma unroll
        for (int i = 0; i < 4; i++) {
            float4 v = ra[i];
            __nv_bfloat16 h0 = __float2bfloat16(v.x), h1 = __float2bfloat16(v.y);
            __nv_bfloat16 h2 = __float2bfloat16(v.z), h3 = __float2bfloat16(v.w);
            __nv_bfloat16 l0 = __float2bfloat16(v.x - __bfloat162float(h0));
            __nv_bfloat16 l1 = __float2bfloat16(v.y - __bfloat162float(h1));
            __nv_bfloat16 l2 = __float2bfloat16(v.z - __bfloat162float(h2));
            __nv_bfloat16 l3 = __float2bfloat16(v.w - __bfloat162float(h3));
            *(__nv_bfloat162*)(dA + 4 * i)              = __halves2bfloat162(h0, h1);
            *(__nv_bfloat162*)(dA + 4 * i + 2)          = __halves2bfloat162(h2, h3);
            *(__nv_bfloat162*)(dA + AELEMS + 4 * i)     = __halves2bfloat162(l0, l1);
            *(__nv_bfloat162*)(dA + AELEMS + 4 * i + 2) = __halves2bfloat162(l2, l3);

            float4 w = rb[i];
            __nv_bfloat16 g0 = __float2bfloat16(w.x), g1 = __float2bfloat16(w.y);
            __nv_bfloat16 g2 = __float2bfloat16(w.z), g3 = __float2bfloat16(w.w);
            __nv_bfloat16 m0 = __float2bfloat16(w.x - __bfloat162float(g0));
            __nv_bfloat16 m1 = __float2bfloat16(w.y - __bfloat162float(g1));
            __nv_bfloat16 m2 = __float2bfloat16(w.z - __bfloat162float(g2));
            __nv_bfloat16 m3 = __float2bfloat16(w.w - __bfloat162float(g3));
            *(__nv_bfloat162*)(dB + 4 * i)              = __halves2bfloat162(g0, g1);
            *(__nv_bfloat162*)(dB + 4 * i + 2)          = __halves2bfloat162(g2, g3);
            *(__nv_bfloat162*)(dB + AELEMS + 4 * i)     = __halves2bfloat162(m0, m1);
            *(__nv_bfloat162*)(dB + AELEMS + 4 * i + 2) = __halves2bfloat162(m2, m3);
        }
    };

    const int arow  = m_base + (lane & 15);
    const int akh   = (lane >> 4) << 3;
    const int brow4 = ((lane >> 4) & 1) * 8 + (lane & 7);   // x4 pair-tile row
    const int bkh4  = ((lane >> 3) & 1) * 8;                // x4 pair-tile k-half

    auto COMPUTE = [&](int s) {
        const uint32_t stA = sb32 + (uint32_t)(s * STAGE_H) * 2;
        const uint32_t stB = stA + (uint32_t)(2 * AELEMS) * 2;
#pragma unroll
        for (int ks = 0; ks < BBK; ks += 16) {
            uint32_t Ah[2][4], Al[2][4];
#pragma unroll
            for (int mt = 0; mt < 2; mt++) {
                uint32_t addr = stA + (uint32_t)((arow + mt * 16) * BSTR + ks + akh) * 2;
                ldsm_x4(Ah[mt], addr);
                ldsm_x4(Al[mt], addr + AELEMS * 2);
            }
#pragma unroll
            for (int t = 0; t < 4; t++) {          // pairs of n8-tiles: {2t, 2t+1}
                uint32_t Bh[4], Bl[4];
                uint32_t addr = stB + (uint32_t)((n_base + t * 16 + brow4) * BSTR + ks + bkh4) * 2;
                ldsm_x4(Bh, addr);
                ldsm_x4(Bl, addr + AELEMS * 2);
#pragma unroll
                for (int mt = 0; mt < 2; mt++) {
                    float* c0p = acc[mt][2 * t];
                    float* c1p = acc[mt][2 * t + 1];
                    mma_bf16(c0p, Ah[mt], Bl);
                    mma_bf16(c0p, Al[mt], Bh);
                    mma_bf16(c0p, Ah[mt], Bh);
                    mma_bf16(c1p, Ah[mt], Bl + 2);
                    mma_bf16(c1p, Al[mt], Bh + 2);
                    mma_bf16(c1p, Ah[mt], Bh + 2);
                }
            }
        }
    };

    const int NC = K / BBK;
    LOAD(0); STORE(0); __syncthreads();
    for (int c = 0; c < NC; c++) {
        const int s = c & 1;
        if (c + 1 < NC) LOAD(c + 1);
        COMPUTE(s);
        if (c + 1 < NC) STORE(s ^ 1);
        __syncthreads();
    }

    const int lq  = lane >> 2;
    const int lr2 = (lane & 3) * 2;
#pragma unroll
    for (int mt = 0; mt < 2; mt++)
#pragma unroll
        for (int nt = 0; nt < 8; nt++) {
            int row = r0 + m_base + mt * 16 + lq;
            int col = c0 + n_base + nt * 8 + lr2;
            *(float2*)(C + (long)row * N + col)       = make_float2(acc[mt][nt][0], acc[mt][nt][1]);
            *(float2*)(C + (long)(row + 8) * N + col) = make_float2(acc[mt][nt][2], acc[mt][nt][3]);
        }
}

// ============================================================================
// bf16-mma causal flash attention — v2: double-buffered K/V + x4 ldmatrix.
// ============================================================================
#define AQB   128
#define AKB   64
#define QSTR  136
#define FA_QHI   0
#define FA_QLO   (128 * QSTR)
#define FA_ST0   (2 * 128 * QSTR)
#define ST_SZ    (3 * 64 * QSTR)
#define ST_KHI   0
#define ST_KLO   (64 * QSTR)
#define ST_V     (2 * 64 * QSTR)
#define FA_SMEM  ((FA_ST0 + 2 * ST_SZ) * 2)   // 174080 bytes

__global__ void __launch_bounds__(256, 1)
flash_attn_mma(const float* __restrict__ q, const float* __restrict__ kv,
               float* __restrict__ o)
{
    extern __shared__ char smraw[];
    __nv_bfloat16* smh = (__nv_bfloat16*)smraw;
    const uint32_t sb32 = smem_u32(smraw);

    const int tid  = threadIdx.x;
    const int lane = tid & 31;
    const int wid  = tid >> 5;
    const int qbi  = gridDim.x - 1 - blockIdx.x;
    const int n    = blockIdx.y;
    const int b    = n >> 3;
    const int h    = n & 7;
    const int q0   = qbi * AQB;
    const float scaling = 0.08838834764831845f;

    // ---- load + scale + split Q ----
    {
        const int lrow = tid >> 1;
        const int cb   = (tid & 1) * 64;
        const float* qp = q + ((long)(q0 + lrow) * B_SZ + b) * P_DIM + h * HD + cb;
        __nv_bfloat16* dH = smh + FA_QHI + lrow * QSTR + cb;
        __nv_bfloat16* dL = smh + FA_QLO + lrow * QSTR + cb;
#pragma unroll
        for (int i = 0; i < 16; i++) {
            float4 v = *(const float4*)(qp + 4 * i);
            v.x *= scaling; v.y *= scaling; v.z *= scaling; v.w *= scaling;
            __nv_bfloat16 h0 = __float2bfloat16(v.x), h1 = __float2bfloat16(v.y);
            __nv_bfloat16 h2 = __float2bfloat16(v.z), h3 = __float2bfloat16(v.w);
            __nv_bfloat16 l0 = __float2bfloat16(v.x - __bfloat162float(h0));
            __nv_bfloat16 l1 = __float2bfloat16(v.y - __bfloat162float(h1));
            __nv_bfloat16 l2 = __float2bfloat16(v.z - __bfloat162float(h2));
            __nv_bfloat16 l3 = __float2bfloat16(v.w - __bfloat162float(h3));
            *(__nv_bfloat162*)(dH + 4 * i)     = __halves2bfloat162(h0, h1);
            *(__nv_bfloat162*)(dH + 4 * i + 2) = __halves2bfloat162(h2, h3);
            *(__nv_bfloat162*)(dL + 4 * i)     = __halves2bfloat162(l0, l1);
            *(__nv_bfloat162*)(dL + 4 * i + 2) = __halves2bfloat162(l2, l3);
        }
    }

    const int lq = lane >> 2;
    const int lr = lane & 3;
    float oacc[16][4];
#pragma unroll
    for (int i = 0; i < 16; i++)
#pragma unroll
        for (int j = 0; j < 4; j++) oacc[i][j] = 0.0f;
    float mA = -1e30f, mB = -1e30f, lA = 0.0f, lB = 0.0f;

    const int arow  = wid * 16 + (lane & 15);
    const int akh   = (lane >> 4) << 3;
    const int brow4 = ((lane >> 4) & 1) * 8 + (lane & 7);
    const int bkh4  = ((lane >> 3) & 1) * 8;
    const int vrow4 = ((lane >> 3) & 1) * 8 + (lane & 7);
    const int vch4  = ((lane >> 4) & 1) * 8;

    const int klrow = tid >> 2;
    const int kcb   = (tid & 3) * 32;
    const long kvstride = (long)AKB * B_SZ * (2 * P_DIM);
    const float* kp0 = kv + ((long)klrow * B_SZ + b) * (2 * P_DIM) + h * HD + kcb;

    float4 rkv[8];

    auto LDG_K = [&](int jb) {
        const float* p = kp0 + (long)jb * kvstride;
#pragma unroll
        for (int i = 0; i < 8; i++) rkv[i] = *(const float4*)(p + 4 * i);
    };
    auto LDG_V = [&](int jb) {
        const float* p = kp0 + (long)jb * kvstride + P_DIM;
#pragma unroll
        for (int i = 0; i < 8; i++) rkv[i] = *(const float4*)(p + 4 * i);
    };
    auto STS_K = [&](int s) {
        __nv_bfloat16* dH = smh + FA_ST0 + s * ST_SZ + ST_KHI + klrow * QSTR + kcb;
        __nv_bfloat16* dL = dH + ST_KLO;
#pragma unroll
        for (int i = 0; i < 8; i++) {
            float4 v = rkv[i];
            __nv_bfloat16 h0 = __float2bfloat16(v.x), h1 = __float2bfloat16(v.y);
            __nv_bfloat16 h2 = __float2bfloat16(v.z), h3 = __float2bfloat16(v.w);
            __nv_bfloat16 l0 = __float2bfloat16(v.x - __bfloat162float(h0));
            __nv_bfloat16 l1 = __float2bfloat16(v.y - __bfloat162float(h1));
            __nv_bfloat16 l2 = __float2bfloat16(v.z - __bfloat162float(h2));
            __nv_bfloat16 l3 = __float2bfloat16(v.w - __bfloat162float(h3));
            *(__nv_bfloat162*)(dH + 4 * i)     = __halves2bfloat162(h0, h1);
            *(__nv_bfloat162*)(dH + 4 * i + 2) = __halves2bfloat162(h2, h3);
            *(__nv_bfloat162*)(dL + 4 * i)     = __halves2bfloat162(l0, l1);
            *(__nv_bfloat162*)(dL + 4 * i + 2) = __halves2bfloat162(l2, l3);
        }
    };
    auto STS_V = [&](int s) {
        __nv_bfloat16* dV = smh + FA_ST0 + s * ST_SZ + ST_V + klrow * QSTR + kcb;
#pragma unroll
        for (int i = 0; i < 8; i++) {
            float4 w = rkv[i];
            *(__nv_bfloat162*)(dV + 4 * i)     = __halves2bfloat162(__float2bfloat16(w.x), __float2bfloat16(w.y));
            *(__nv_bfloat162*)(dV + 4 * i + 2) = __halves2bfloat162(__float2bfloat16(w.z), __float2bfloat16(w.w));
        }
    };

    LDG_K(0); STS_K(0); LDG_V(0); STS_V(0);
    __syncthreads();

    const int nkb = 2 * qbi + 2;
    for (int jb = 0; jb < nkb; jb++) {
        const int s = jb & 1;
        const bool pre = (jb + 1 < nkb);
        const uint32_t stage = sb32 + (uint32_t)(FA_ST0 + s * ST_SZ) * 2;

        if (pre) LDG_K(jb + 1);

        float sacc[8][4];
#pragma unroll
        for (int i = 0; i < 8; i++)
#pragma unroll
            for (int j = 0; j < 4; j++) sacc[i][j] = 0.0f;

#pragma unroll
        for (int ks = 0; ks < 8; ks++) {
            uint32_t Ah[4], Al[4];
            uint32_t aaddr = sb32 + (uint32_t)(arow * QSTR + ks * 16 + akh) * 2;
            ldsm_x4(Ah, aaddr + FA_QHI * 2);
            ldsm_x4(Al, aaddr + FA_QLO * 2);
#pragma unroll
            for (int nt2 = 0; nt2 < 4; nt2++) {
                uint32_t Bh[4], Bl[4];
                uint32_t baddr = stage + (uint32_t)(ST_KHI + (nt2 * 16 + brow4) * QSTR + ks * 16 + bkh4) * 2;
                ldsm_x4(Bh, baddr);
                ldsm_x4(Bl, baddr + ST_KLO * 2);
                mma_bf16(sacc[2 * nt2],     Ah, Bl);
                mma_bf16(sacc[2 * nt2],     Al, Bh);
                mma_bf16(sacc[2 * nt2],     Ah, Bh);
                mma_bf16(sacc[2 * nt2 + 1], Ah, Bl + 2);
                mma_bf16(sacc[2 * nt2 + 1], Al, Bh + 2);
                mma_bf16(sacc[2 * nt2 + 1], Ah, Bh + 2);
            }
        }

        if (pre) { STS_K(s ^ 1); LDG_V(jb + 1); }

        const int j0 = jb * AKB;
        if (j0 + AKB - 1 > q0) {
            const int rowA = q0 + wid * 16 + lq;
            const int rowB = rowA + 8;
#pragma unroll
            for (int nt = 0; nt < 8; nt++) {
                int col = j0 + nt * 8 + 2 * lr;
                if (col     > rowA) sacc[nt][0] = -1e30f;
                if (col + 1 > rowA) sacc[nt][1] = -1e30f;
                if (col     > rowB) sacc[nt][2] = -1e30f;
                if (col + 1 > rowB) sacc[nt][3] = -1e30f;
            }
        }

        float nmA = -1e30f, nmB = -1e30f;
#pragma unroll
        for (int nt = 0; nt < 8; nt++) {
            nmA = fmaxf(nmA, fmaxf(sacc[nt][0], sacc[nt][1]));
            nmB = fmaxf(nmB, fmaxf(sacc[nt][2], sacc[nt][3]));
        }
        nmA = fmaxf(nmA, __shfl_xor_sync(0xffffffffu, nmA, 1));
        nmA = fmaxf(nmA, __shfl_xor_sync(0xffffffffu, nmA, 2));
        nmB = fmaxf(nmB, __shfl_xor_sync(0xffffffffu, nmB, 1));
        nmB = fmaxf(nmB, __shfl_xor_sync(0xffffffffu, nmB, 2));

        float m2A = fmaxf(mA, nmA), m2B = fmaxf(mB, nmB);
        float rsA = __expf(mA - m2A), rsB = __expf(mB - m2B);
        mA = m2A; mB = m2B;

        float sumA = 0.0f, sumB = 0.0f;
        uint32_t aP[4][4];
#pragma unroll
        for (int g = 0; g < 4; g++) {
            float p00 = __expf(sacc[2*g][0]   - m2A);
            float p01 = __expf(sacc[2*g][1]   - m2A);
            float p02 = __expf(sacc[2*g][2]   - m2B);
            float p03 = __expf(sacc[2*g][3]   - m2B);
            float p10 = __expf(sacc[2*g+1][0] - m2A);
            float p11 = __expf(sacc[2*g+1][1] - m2A);
            float p12 = __expf(sacc[2*g+1][2] - m2B);
            float p13 = __expf(sacc[2*g+1][3] - m2B);
            sumA += p00 + p01 + p10 + p11;
            sumB += p02 + p03 + p12 + p13;
            aP[g][0] = pk_bf2(p00, p01);
            aP[g][1] = pk_bf2(p02, p03);
            aP[g][2] = pk_bf2(p10, p11);
            aP[g][3] = pk_bf2(p12, p13);
        }
        sumA += __shfl_xor_sync(0xffffffffu, sumA, 1);
        sumA += __shfl_xor_sync(0xffffffffu, sumA, 2);
        sumB += __shfl_xor_sync(0xffffffffu, sumB, 1);
        sumB += __shfl_xor_sync(0xffffffffu, sumB, 2);
        lA = lA * rsA + sumA;
        lB = lB * rsB + sumB;

#pragma unroll
        for (int nt = 0; nt < 16; nt++) {
            oacc[nt][0] *= rsA; oacc[nt][1] *= rsA;
            oacc[nt][2] *= rsB; oacc[nt][3] *= rsB;
        }
#pragma unroll
        for (int g = 0; g < 4; g++) {
#pragma unroll
            for (int nt2 = 0; nt2 < 8; nt2++) {
                uint32_t Bv[4];
                uint32_t vaddr = stage + (uint32_t)(ST_V + (g * 16 + vrow4) * QSTR + nt2 * 16 + vch4) * 2;
                ldsm_x4_t(Bv, vaddr);
                mma_bf16(oacc[2 * nt2],     aP[g], Bv);
                mma_bf16(oacc[2 * nt2 + 1], aP[g], Bv + 2);
            }
        }

        if (pre) STS_V(s ^ 1);
        __syncthreads();
    }

    {
        const float iA = 1.0f / lA, iB = 1.0f / lB;
        const int rowA = q0 + wid * 16 + lq;
        const int rowB = rowA + 8;
        float* dA = o + ((long)rowA * B_SZ + b) * P_DIM + h * HD;
        float* dB = o + ((long)rowB * B_SZ + b) * P_DIM + h * HD;
#pragma unroll
        for (int nt = 0; nt < 16; nt++) {
            int col = nt * 8 + 2 * lr;
            *(float2*)(dA + col) = make_float2(oacc[nt][0] * iA, oacc[nt][1] * iA);
            *(float2*)(dB + col) = make_float2(oacc[nt][2] * iB, oacc[nt][3] * iB);
        }
    }
}

// ============================================================================
// rezero residual + LayerNorm (unchanged)
// ============================================================================
__global__ void __launch_bounds__(256)
rezero_ln(const float* __restrict__ att, const float* __restrict__ res,
          const float* __restrict__ alpha, const float* __restrict__ w,
          const float* __restrict__ bia, float* __restrict__ out)
{
    __shared__ float red[8];
    const int row = blockIdx.x;
    const int tid = threadIdx.x;
    const int lane = tid & 31, warp = tid >> 5;
    const float a = alpha[0];

    float4 x4 = *(const float4*)(att + (long)row * P_DIM + tid * 4);
    float4 r4 = *(const float4*)(res + (long)row * P_DIM + tid * 4);
    float v[4] = { a * x4.x + r4.x, a * x4.y + r4.y,
                   a * x4.z + r4.z, a * x4.w + r4.w };

    float s = v[0] + v[1] + v[2] + v[3];
#pragma unroll
    for (int off = 16; off >= 1; off >>= 1) s += __shfl_xor_sync(0xffffffffu, s, off);
    if (lane == 0) red[warp] = s;
    __syncthreads();
    s = red[0] + red[1] + red[2] + red[3] + red[4] + red[5] + red[6] + red[7];
    const float mu = s * (1.0f / P_DIM);

    float d0 = v[0] - mu, d1 = v[1] - mu, d2 = v[2] - mu, d3 = v[3] - mu;
    float ss = d0 * d0 + d1 * d1 + d2 * d2 + d3 * d3;
#pragma unroll
    for (int off = 16; off >= 1; off >>= 1) ss += __shfl_xor_sync(0xffffffffu, ss, off);
    __syncthreads();
    if (lane == 0) red[warp] = ss;
    __syncthreads();
    ss = red[0] + red[1] + red[2] + red[3] + red[4] + red[5] + red[6] + red[7];
    const float inv = rsqrtf(ss * (1.0f / P_DIM) + LN_EPS);

    float4 w4 = *(const float4*)(w  + tid * 4);
    float4 b4 = *(const float4*)(bia + tid * 4);
    float4 o4 = make_float4(d0 * inv * w4.x + b4.x, d1 * inv * w4.y + b4.y,
                            d2 * inv * w4.z + b4.z, d3 * inv * w4.w + b4.w);
    *(float4*)(out + (long)row * P_DIM + tid * 4) = o4;
}

// ============================================================================
// launch
// ============================================================================
extern "C" void kernel_launch(void* const* d_in, const int* in_sizes, int n_in,
                              void* d_out, int out_size)
{
    const float* input = (const float*)d_in[0];
    const float* W1    = (const float*)d_in[2];
    const float* W2    = (const float*)d_in[3];
    const float* W3    = (const float*)d_in[4];
    const float* alpha = (const float*)d_in[5];
    const float* ln_w  = (const float*)d_in[6];
    const float* ln_b  = (const float*)d_in[7];
    float* out = (float*)d_out;

    float *q, *kv, *att, *oln;
    cudaGetSymbolAddress((void**)&q,   g_q);
    cudaGetSymbolAddress((void**)&kv,  g_kv);
    cudaGetSymbolAddress((void**)&att, g_att);
    cudaGetSymbolAddress((void**)&oln, g_oln);

    cudaFuncSetAttribute(gemm_bf16x3,    cudaFuncAttributeMaxDynamicSharedMemorySize, GB_SMEM);
    cudaFuncSetAttribute(flash_attn_mma, cudaFuncAttributeMaxDynamicSharedMemorySize, FA_SMEM);

    gemm_bf16x3<<<dim3(P_DIM / 128, M_ROWS / 128), 256, GB_SMEM>>>(input, W1, q, M_ROWS, P_DIM, D_INF);
    gemm_bf16x3<<<dim3(2 * P_DIM / 128, M_ROWS / 128), 256, GB_SMEM>>>(q, W2, kv, M_ROWS, 2 * P_DIM, P_DIM);
    flash_attn_mma<<<dim3(L_SEQ / AQB, B_SZ * H_HEADS), 256, FA_SMEM>>>(q, kv, att);
    rezero_ln<<<M_ROWS, 256>>>(att, q, alpha, ln_w, ln_b, oln);
    gemm_bf16x3<<<dim3(D_OUTF / 128, M_ROWS / 128), 256, GB_SMEM>>>(oln, W3, out, M_ROWS, D_OUTF, P_DIM);
}